// round 4
// baseline (speedup 1.0000x reference)
#include <cuda_runtime.h>
#include <cuda_bf16.h>
#include <cstdint>

#define NN 100000
#define NE 3200000
#define INF 512
#define HID 16

// ---------------- scratch (no allocs allowed) ----------------
__device__ __align__(16) float g_deg_out[NN];   // becomes norm_src in place
__device__ __align__(16) float g_deg_in[NN];    // becomes norm_dst in place
__device__ __align__(16) float g_h1[NN * 16];   // layer-1 projected (pre-agg)
__device__ __align__(16) float g_agg1[NN * 16];
__device__ __align__(16) float g_x16[NN * 16];  // relu(...)*norm_src
__device__ __align__(16) float g_agg2[NN * 16];
__device__ __align__(16) int2  g_edges[NE];
__device__ float g_Weff[48];   // (W2 @ Wfc) [16,3]
__device__ float g_beff[3];    // b2 @ Wfc + bfc
__device__ int   g_is64;

// vector reduction to global (sm_90+)
__device__ __forceinline__ void red_add_v4(float* addr, float4 v) {
    asm volatile("red.global.add.v4.f32 [%0], {%1, %2, %3, %4};"
                 :: "l"(addr), "f"(v.x), "f"(v.y), "f"(v.z), "f"(v.w)
                 : "memory");
}

// ---------------- kernels ----------------

// Detect whether edge indices are int64 or int32. True int64 indices are all
// < 100000; if the buffer is really int32 pairs, an int64 view is >= 2^32
// unless the odd int32 happens to be 0 (p ~ 1e-5 per elem; 16 elems => safe).
__global__ void detect_kernel(const unsigned long long* __restrict__ src) {
    if (blockIdx.x == 0 && threadIdx.x == 0) {
        int ok = 1;
        #pragma unroll
        for (int i = 0; i < 16; i++)
            if (src[i] >= 100000ull) ok = 0;
        g_is64 = ok;
    }
}

__global__ void zero_kernel() {
    int i  = blockIdx.x * blockDim.x + threadIdx.x;
    int st = gridDim.x * blockDim.x;
    for (int j = i; j < NN; j += st) { g_deg_out[j] = 0.f; g_deg_in[j] = 0.f; }
    float4 z = make_float4(0.f, 0.f, 0.f, 0.f);
    float4* a1 = reinterpret_cast<float4*>(g_agg1);
    float4* a2 = reinterpret_cast<float4*>(g_agg2);
    for (int j = i; j < NN * 4; j += st) { a1[j] = z; a2[j] = z; }
}

__global__ void pack_deg_kernel(const void* __restrict__ srcv,
                                const void* __restrict__ dstv) {
    int i = blockIdx.x * blockDim.x + threadIdx.x;
    if (i >= NE) return;
    int s, d;
    if (g_is64) {
        s = (int)((const long long*)srcv)[i];
        d = (int)((const long long*)dstv)[i];
    } else {
        s = ((const int*)srcv)[i];
        d = ((const int*)dstv)[i];
    }
    g_edges[i] = make_int2(s, d);
    atomicAdd(&g_deg_out[s], 1.0f);
    atomicAdd(&g_deg_in[d], 1.0f);
}

__global__ void norm_kernel() {
    int i = blockIdx.x * blockDim.x + threadIdx.x;
    if (i < NN) {
        g_deg_out[i] = rsqrtf(fmaxf(g_deg_out[i], 1.0f));  // norm_src
        g_deg_in[i]  = rsqrtf(fmaxf(g_deg_in[i], 1.0f));   // norm_dst
    }
}

// h1[n][:] = (feat[n][:] @ W1) * norm_src[n]   (scale folded into output)
// One warp computes 4 nodes; W1^T staged in smem; log2 shuffle reduction.
__global__ __launch_bounds__(256) void gemm1_kernel(const float* __restrict__ feat,
                                                    const float* __restrict__ W1) {
    __shared__ float sW[16 * 512];  // sW[j*512 + k] = W1[k][j]
    for (int i = threadIdx.x; i < 8192; i += blockDim.x) {
        int k = i & 511, j = i >> 9;
        sW[j * 512 + k] = W1[k * 16 + j];
    }
    __syncthreads();

    int lane = threadIdx.x & 31;
    int gw   = (blockIdx.x * blockDim.x + threadIdx.x) >> 5;
    int n0   = gw * 4;
    if (n0 >= NN) return;

    float acc[4][16];
    #pragma unroll
    for (int nd = 0; nd < 4; nd++)
        #pragma unroll
        for (int j = 0; j < 16; j++) acc[nd][j] = 0.f;

    #pragma unroll
    for (int i = 0; i < 4; i++) {
        int kb = i * 128 + lane * 4;
        float4 f[4];
        #pragma unroll
        for (int nd = 0; nd < 4; nd++) {
            int n = n0 + nd;
            f[nd] = (n < NN)
                ? *reinterpret_cast<const float4*>(feat + (size_t)n * INF + kb)
                : make_float4(0.f, 0.f, 0.f, 0.f);
        }
        #pragma unroll
        for (int j = 0; j < 16; j++) {
            float4 w = *reinterpret_cast<const float4*>(sW + j * 512 + kb);
            #pragma unroll
            for (int nd = 0; nd < 4; nd++) {
                acc[nd][j] = fmaf(f[nd].x, w.x, acc[nd][j]);
                acc[nd][j] = fmaf(f[nd].y, w.y, acc[nd][j]);
                acc[nd][j] = fmaf(f[nd].z, w.z, acc[nd][j]);
                acc[nd][j] = fmaf(f[nd].w, w.w, acc[nd][j]);
            }
        }
    }

    // Fold 16 regs x 32 lanes -> 16 sums (lane l ends with feature brev4(l)).
    int jf = (int)(__brev((unsigned)lane) >> 28);
    #pragma unroll
    for (int nd = 0; nd < 4; nd++) {
        #pragma unroll
        for (int s = 0; s < 4; s++) {
            int half = 8 >> s;                 // 8,4,2,1
            bool up = (lane >> s) & 1;
            #pragma unroll
            for (int j = 0; j < half; j++) {
                float send = up ? acc[nd][j] : acc[nd][j + half];
                float keep = up ? acc[nd][j + half] : acc[nd][j];
                float recv = __shfl_xor_sync(0xffffffffu, send, 1 << s);
                acc[nd][j] = keep + recv;
            }
        }
        float v = acc[nd][0] + __shfl_xor_sync(0xffffffffu, acc[nd][0], 16);
        int n = n0 + nd;
        if (lane < 16 && n < NN)
            g_h1[(size_t)n * 16 + jf] = v * g_deg_out[n];
    }
}

// agg[dst] += tbl[src]  (16 floats per edge, vector red)
__global__ void edge_pass_kernel(int pass) {
    int i = blockIdx.x * blockDim.x + threadIdx.x;
    if (i >= NE) return;
    int2 e = g_edges[i];
    const float* tbl = pass ? g_x16 : g_h1;
    float*       agg = pass ? g_agg2 : g_agg1;
    const float4* h = reinterpret_cast<const float4*>(tbl + (size_t)e.x * 16);
    float4 a0 = __ldg(h + 0), a1 = __ldg(h + 1), a2 = __ldg(h + 2), a3 = __ldg(h + 3);
    float* d = agg + (size_t)e.y * 16;
    red_add_v4(d + 0,  a0);
    red_add_v4(d + 4,  a1);
    red_add_v4(d + 8,  a2);
    red_add_v4(d + 12, a3);
}

// x16[n] = relu(agg1[n]*norm_dst[n] + b1) * norm_src[n]   (pre-scale for L2)
__global__ void relu_kernel(const float* __restrict__ b1) {
    int n = blockIdx.x * blockDim.x + threadIdx.x;
    if (n >= NN) return;
    float ns = g_deg_out[n], nd = g_deg_in[n];
    const float4* a = reinterpret_cast<const float4*>(g_agg1 + (size_t)n * 16);
    float4*       x = reinterpret_cast<float4*>(g_x16 + (size_t)n * 16);
    #pragma unroll
    for (int r = 0; r < 4; r++) {
        float4 v = a[r];
        v.x = fmaxf(fmaf(v.x, nd, __ldg(&b1[r * 4 + 0])), 0.f) * ns;
        v.y = fmaxf(fmaf(v.y, nd, __ldg(&b1[r * 4 + 1])), 0.f) * ns;
        v.z = fmaxf(fmaf(v.z, nd, __ldg(&b1[r * 4 + 2])), 0.f) * ns;
        v.w = fmaxf(fmaf(v.w, nd, __ldg(&b1[r * 4 + 3])), 0.f) * ns;
        x[r] = v;
    }
}

// Weff = W2 @ Wfc  [16,3];  beff = b2 @ Wfc + bfc
__global__ void weff_kernel(const float* __restrict__ W2, const float* __restrict__ b2,
                            const float* __restrict__ Wfc, const float* __restrict__ bfc) {
    int t = threadIdx.x;
    if (t < 48) {
        int i = t / 3, c = t % 3;
        float s = 0.f;
        for (int o = 0; o < 128; o++) s = fmaf(W2[i * 128 + o], Wfc[o * 3 + c], s);
        g_Weff[t] = s;
    } else if (t < 51) {
        int c = t - 48;
        float s = bfc[c];
        for (int o = 0; o < 128; o++) s = fmaf(b2[o], Wfc[o * 3 + c], s);
        g_beff[c] = s;
    }
}

// out[n][:] = (agg2[n]*norm_dst[n]) @ Weff + beff
__global__ void final_kernel(float* __restrict__ out) {
    int n = blockIdx.x * blockDim.x + threadIdx.x;
    if (n >= NN) return;
    float nd = g_deg_in[n];
    const float4* a4 = reinterpret_cast<const float4*>(g_agg2 + (size_t)n * 16);
    float a[16];
    #pragma unroll
    for (int r = 0; r < 4; r++) {
        float4 v = a4[r];
        a[r * 4 + 0] = v.x * nd; a[r * 4 + 1] = v.y * nd;
        a[r * 4 + 2] = v.z * nd; a[r * 4 + 3] = v.w * nd;
    }
    float o0 = g_beff[0], o1 = g_beff[1], o2 = g_beff[2];
    #pragma unroll
    for (int i = 0; i < 16; i++) {
        o0 = fmaf(a[i], g_Weff[i * 3 + 0], o0);
        o1 = fmaf(a[i], g_Weff[i * 3 + 1], o1);
        o2 = fmaf(a[i], g_Weff[i * 3 + 2], o2);
    }
    out[(size_t)n * 3 + 0] = o0;
    out[(size_t)n * 3 + 1] = o1;
    out[(size_t)n * 3 + 2] = o2;
}

// ---------------- launch ----------------
extern "C" void kernel_launch(void* const* d_in, const int* in_sizes, int n_in,
                              void* d_out, int out_size) {
    const float* feat = (const float*)d_in[0];
    const void*  src  = d_in[1];
    const void*  dst  = d_in[2];
    const float* W1   = (const float*)d_in[3];
    const float* b1   = (const float*)d_in[4];
    const float* W2   = (const float*)d_in[5];
    const float* b2   = (const float*)d_in[6];
    const float* Wfc  = (const float*)d_in[7];
    const float* bfc  = (const float*)d_in[8];
    float* out = (float*)d_out;

    const int TPB = 256;
    const int nodeBlocks = (NN + TPB - 1) / TPB;
    const int edgeBlocks = (NE + TPB - 1) / TPB;
    const int gemmBlocks = ((NN + 3) / 4 * 32 + TPB - 1) / TPB;  // warp per 4 nodes

    detect_kernel<<<1, 32>>>((const unsigned long long*)src);
    zero_kernel<<<512, TPB>>>();
    pack_deg_kernel<<<edgeBlocks, TPB>>>(src, dst);
    norm_kernel<<<nodeBlocks, TPB>>>();
    weff_kernel<<<1, 64>>>(W2, b2, Wfc, bfc);
    gemm1_kernel<<<gemmBlocks, TPB>>>(feat, W1);
    edge_pass_kernel<<<edgeBlocks, TPB>>>(0);
    relu_kernel<<<nodeBlocks, TPB>>>(b1);
    edge_pass_kernel<<<edgeBlocks, TPB>>>(1);
    final_kernel<<<nodeBlocks, TPB>>>(out);
}

// round 8
// speedup vs baseline: 1.2640x; 1.2640x over previous
#include <cuda_runtime.h>
#include <cuda_bf16.h>
#include <cstdint>

#define NN 100000
#define NE 3200000
#define INF 512

// ---------------- scratch (no allocs allowed) ----------------
__device__ __align__(16) int   g_deg_out[NN];
__device__ __align__(16) int   g_deg_in[NN];
__device__ __align__(16) float g_nsrc[NN];      // rsqrt(max(deg_out,1))
__device__ __align__(16) float g_ndst[NN];      // rsqrt(max(deg_in,1))
__device__ __align__(16) float g_h1[NN * 16];   // (feat @ W1) * nsrc
__device__ __align__(16) float g_x16[NN * 16];  // relu(agg1*nd + b1) * ns
__device__ __align__(16) int   g_csr_src[NE];   // src ids grouped by dst
__device__ int   g_csr_beg[NN];
__device__ int   g_csr_pos[NN];
__device__ int   g_cursor;
__device__ float g_Weff[48];   // (W2 @ Wfc) [16,3]
__device__ float g_beff[3];    // b2 @ Wfc + bfc
__device__ int   g_is64;

// ---------------- kernels ----------------

// Detect int64 vs int32 edge indices (values < 100000 => an int64 view is
// >= 2^32 unless genuinely int64; 16 elems => misdetection ~impossible).
__global__ void detect_kernel(const unsigned long long* __restrict__ src) {
    if (blockIdx.x == 0 && threadIdx.x == 0) {
        int ok = 1;
        #pragma unroll
        for (int i = 0; i < 16; i++)
            if (src[i] >= 100000ull) ok = 0;
        g_is64 = ok;
        g_cursor = 0;
    }
}

__global__ void zero_kernel() {
    int i  = blockIdx.x * blockDim.x + threadIdx.x;
    int st = gridDim.x * blockDim.x;
    for (int j = i; j < NN; j += st) { g_deg_out[j] = 0; g_deg_in[j] = 0; }
}

__global__ void deg_kernel(const void* __restrict__ srcv,
                           const void* __restrict__ dstv) {
    int i = blockIdx.x * blockDim.x + threadIdx.x;
    if (i >= NE) return;
    int s, d;
    if (g_is64) {
        s = (int)((const long long*)srcv)[i];
        d = (int)((const long long*)dstv)[i];
    } else {
        s = ((const int*)srcv)[i];
        d = ((const int*)dstv)[i];
    }
    atomicAdd(&g_deg_out[s], 1);
    atomicAdd(&g_deg_in[d], 1);
}

// norms + CSR region assignment (rows need not be in node order)
__global__ void alloc_kernel() {
    int n = blockIdx.x * blockDim.x + threadIdx.x;
    if (n >= NN) return;
    int di = g_deg_in[n];
    g_nsrc[n] = rsqrtf(fmaxf((float)g_deg_out[n], 1.0f));
    g_ndst[n] = rsqrtf(fmaxf((float)di, 1.0f));
    int beg = atomicAdd(&g_cursor, di);
    g_csr_beg[n] = beg;
    g_csr_pos[n] = beg;
}

__global__ void scatter_kernel(const void* __restrict__ srcv,
                               const void* __restrict__ dstv) {
    int i = blockIdx.x * blockDim.x + threadIdx.x;
    if (i >= NE) return;
    int s, d;
    if (g_is64) {
        s = (int)((const long long*)srcv)[i];
        d = (int)((const long long*)dstv)[i];
    } else {
        s = ((const int*)srcv)[i];
        d = ((const int*)dstv)[i];
    }
    int p = atomicAdd(&g_csr_pos[d], 1);
    g_csr_src[p] = s;
}

// h1[n][:] = (feat[n][:] @ W1) * nsrc[n]
__global__ __launch_bounds__(256) void gemm1_kernel(const float* __restrict__ feat,
                                                    const float* __restrict__ W1) {
    __shared__ float sW[16 * 512];  // sW[j*512 + k] = W1[k][j]
    for (int i = threadIdx.x; i < 8192; i += blockDim.x) {
        int k = i & 511, j = i >> 9;
        sW[j * 512 + k] = W1[k * 16 + j];
    }
    __syncthreads();

    int lane = threadIdx.x & 31;
    int gw   = (blockIdx.x * blockDim.x + threadIdx.x) >> 5;
    int n0   = gw * 4;
    if (n0 >= NN) return;

    float acc[4][16];
    #pragma unroll
    for (int nd = 0; nd < 4; nd++)
        #pragma unroll
        for (int j = 0; j < 16; j++) acc[nd][j] = 0.f;

    #pragma unroll
    for (int i = 0; i < 4; i++) {
        int kb = i * 128 + lane * 4;
        float4 f[4];
        #pragma unroll
        for (int nd = 0; nd < 4; nd++) {
            int n = n0 + nd;
            f[nd] = (n < NN)
                ? *reinterpret_cast<const float4*>(feat + (size_t)n * INF + kb)
                : make_float4(0.f, 0.f, 0.f, 0.f);
        }
        #pragma unroll
        for (int j = 0; j < 16; j++) {
            float4 w = *reinterpret_cast<const float4*>(sW + j * 512 + kb);
            #pragma unroll
            for (int nd = 0; nd < 4; nd++) {
                acc[nd][j] = fmaf(f[nd].x, w.x, acc[nd][j]);
                acc[nd][j] = fmaf(f[nd].y, w.y, acc[nd][j]);
                acc[nd][j] = fmaf(f[nd].z, w.z, acc[nd][j]);
                acc[nd][j] = fmaf(f[nd].w, w.w, acc[nd][j]);
            }
        }
    }

    int jf = (int)(__brev((unsigned)lane) >> 28);
    #pragma unroll
    for (int nd = 0; nd < 4; nd++) {
        #pragma unroll
        for (int s = 0; s < 4; s++) {
            int half = 8 >> s;
            bool up = (lane >> s) & 1;
            #pragma unroll
            for (int j = 0; j < half; j++) {
                float send = up ? acc[nd][j] : acc[nd][j + half];
                float keep = up ? acc[nd][j + half] : acc[nd][j];
                float recv = __shfl_xor_sync(0xffffffffu, send, 1 << s);
                acc[nd][j] = keep + recv;
            }
        }
        float v = acc[nd][0] + __shfl_xor_sync(0xffffffffu, acc[nd][0], 16);
        int n = n0 + nd;
        if (lane < 16 && n < NN)
            g_h1[(size_t)n * 16 + jf] = v * g_nsrc[n];
    }
}

// Weff = W2 @ Wfc  [16,3];  beff = b2 @ Wfc + bfc
__global__ void weff_kernel(const float* __restrict__ W2, const float* __restrict__ b2,
                            const float* __restrict__ Wfc, const float* __restrict__ bfc) {
    int t = threadIdx.x;
    if (t < 48) {
        int i = t / 3, c = t % 3;
        float s = 0.f;
        for (int o = 0; o < 128; o++) s = fmaf(W2[i * 128 + o], Wfc[o * 3 + c], s);
        g_Weff[t] = s;
    } else if (t < 51) {
        int c = t - 48;
        float s = bfc[c];
        for (int o = 0; o < 128; o++) s = fmaf(b2[o], Wfc[o * 3 + c], s);
        g_beff[c] = s;
    }
}

// Warp-per-node gather-aggregate over the CSR row.
// Lane layout: edge-slot es = lane>>2 (8 slots), chunk c = lane&3.
// Per iteration: 16 edges processed. Edge indices for slot group are loaded
// by lanes 0..15 (one LDG per distinct index) and shfl-broadcast, so the
// LSU issues 16 index loads + 64 vector loads per 16 edges, not 128+64.
template <bool PASS2>
__device__ __forceinline__ void agg_row(int w, int lane,
                                        const float* __restrict__ tbl,
                                        float4& acc) {
    int c = lane & 3, es = lane >> 2;
    int beg = g_csr_beg[w];
    int deg = g_deg_in[w];
    int e = 0;

    // main loop: 16 edges per iteration, indices prefetched by lanes 0..15
    for (; e + 16 <= deg; e += 16) {
        int myidx = 0;
        if (lane < 16) myidx = __ldg(&g_csr_src[beg + e + lane]);
        int s0 = __shfl_sync(0xffffffffu, myidx, es);
        int s1 = __shfl_sync(0xffffffffu, myidx, es + 8);
        float4 v0 = __ldg(reinterpret_cast<const float4*>(tbl + (size_t)s0 * 16) + c);
        float4 v1 = __ldg(reinterpret_cast<const float4*>(tbl + (size_t)s1 * 16) + c);
        acc.x += v0.x + v1.x; acc.y += v0.y + v1.y;
        acc.z += v0.z + v1.z; acc.w += v0.w + v1.w;
    }
    // tail: one edge per slot
    for (int t = e + es; t < deg; t += 8) {
        int s = __ldg(&g_csr_src[beg + t]);
        float4 v = __ldg(reinterpret_cast<const float4*>(tbl + (size_t)s * 16) + c);
        acc.x += v.x; acc.y += v.y; acc.z += v.z; acc.w += v.w;
    }
    // fold the 8 edge-slots: after this every lane holds the full chunk-c sum
    #pragma unroll
    for (int m = 4; m < 32; m <<= 1) {
        acc.x += __shfl_xor_sync(0xffffffffu, acc.x, m);
        acc.y += __shfl_xor_sync(0xffffffffu, acc.y, m);
        acc.z += __shfl_xor_sync(0xffffffffu, acc.z, m);
        acc.w += __shfl_xor_sync(0xffffffffu, acc.w, m);
    }
}

// Pass 1: x16[n] = relu(agg1*ndst + b1) * nsrc   (fused epilogue)
__global__ __launch_bounds__(256) void agg1_kernel(const float* __restrict__ b1) {
    int w = (blockIdx.x * blockDim.x + threadIdx.x) >> 5;
    if (w >= NN) return;
    int lane = threadIdx.x & 31;
    float4 acc = make_float4(0.f, 0.f, 0.f, 0.f);
    agg_row<false>(w, lane, g_h1, acc);
    if (lane < 4) {
        int c = lane;
        float nd = g_ndst[w], ns = g_nsrc[w];
        float4 b = __ldg(reinterpret_cast<const float4*>(b1) + c);
        float4 o;
        o.x = fmaxf(fmaf(acc.x, nd, b.x), 0.f) * ns;
        o.y = fmaxf(fmaf(acc.y, nd, b.y), 0.f) * ns;
        o.z = fmaxf(fmaf(acc.z, nd, b.z), 0.f) * ns;
        o.w = fmaxf(fmaf(acc.w, nd, b.w), 0.f) * ns;
        reinterpret_cast<float4*>(g_x16 + (size_t)w * 16)[c] = o;
    }
}

// Pass 2: out[n] = (agg2*ndst) @ Weff + beff   (fused 16x3 matvec)
__global__ __launch_bounds__(256) void agg2_kernel(float* __restrict__ out) {
    int w = (blockIdx.x * blockDim.x + threadIdx.x) >> 5;
    if (w >= NN) return;
    int lane = threadIdx.x & 31;
    float4 acc = make_float4(0.f, 0.f, 0.f, 0.f);
    agg_row<true>(w, lane, g_x16, acc);

    int c = lane & 3;
    float nd = g_ndst[w];
    float a0 = acc.x * nd, a1 = acc.y * nd, a2 = acc.z * nd, a3 = acc.w * nd;
    int base = c * 4;
    float o0 = 0.f, o1 = 0.f, o2 = 0.f;
    o0 = fmaf(a0, g_Weff[(base + 0) * 3 + 0], o0);
    o1 = fmaf(a0, g_Weff[(base + 0) * 3 + 1], o1);
    o2 = fmaf(a0, g_Weff[(base + 0) * 3 + 2], o2);
    o0 = fmaf(a1, g_Weff[(base + 1) * 3 + 0], o0);
    o1 = fmaf(a1, g_Weff[(base + 1) * 3 + 1], o1);
    o2 = fmaf(a1, g_Weff[(base + 1) * 3 + 2], o2);
    o0 = fmaf(a2, g_Weff[(base + 2) * 3 + 0], o0);
    o1 = fmaf(a2, g_Weff[(base + 2) * 3 + 1], o1);
    o2 = fmaf(a2, g_Weff[(base + 2) * 3 + 2], o2);
    o0 = fmaf(a3, g_Weff[(base + 3) * 3 + 0], o0);
    o1 = fmaf(a3, g_Weff[(base + 3) * 3 + 1], o1);
    o2 = fmaf(a3, g_Weff[(base + 3) * 3 + 2], o2);
    #pragma unroll
    for (int m = 1; m < 4; m <<= 1) {
        o0 += __shfl_xor_sync(0xffffffffu, o0, m);
        o1 += __shfl_xor_sync(0xffffffffu, o1, m);
        o2 += __shfl_xor_sync(0xffffffffu, o2, m);
    }
    if (lane == 0) {
        out[(size_t)w * 3 + 0] = o0 + g_beff[0];
        out[(size_t)w * 3 + 1] = o1 + g_beff[1];
        out[(size_t)w * 3 + 2] = o2 + g_beff[2];
    }
}

// ---------------- launch ----------------
extern "C" void kernel_launch(void* const* d_in, const int* in_sizes, int n_in,
                              void* d_out, int out_size) {
    const float* feat = (const float*)d_in[0];
    const void*  src  = d_in[1];
    const void*  dst  = d_in[2];
    const float* W1   = (const float*)d_in[3];
    const float* b1   = (const float*)d_in[4];
    const float* W2   = (const float*)d_in[5];
    const float* b2   = (const float*)d_in[6];
    const float* Wfc  = (const float*)d_in[7];
    const float* bfc  = (const float*)d_in[8];
    float* out = (float*)d_out;

    const int TPB = 256;
    const int nodeBlocks = (NN + TPB - 1) / TPB;
    const int edgeBlocks = (NE + TPB - 1) / TPB;
    const int gemmBlocks = ((NN + 3) / 4 * 32 + TPB - 1) / TPB;   // warp / 4 nodes
    const int aggBlocks  = (NN * 32 + TPB - 1) / TPB;             // warp / node

    detect_kernel<<<1, 32>>>((const unsigned long long*)src);
    zero_kernel<<<512, TPB>>>();
    deg_kernel<<<edgeBlocks, TPB>>>(src, dst);
    alloc_kernel<<<nodeBlocks, TPB>>>();
    weff_kernel<<<1, 64>>>(W2, b2, Wfc, bfc);
    scatter_kernel<<<edgeBlocks, TPB>>>(src, dst);
    gemm1_kernel<<<gemmBlocks, TPB>>>(feat, W1);
    agg1_kernel<<<aggBlocks, TPB>>>(b1);
    agg2_kernel<<<aggBlocks, TPB>>>(out);
}